// round 1
// baseline (speedup 1.0000x reference)
#include <cuda_runtime.h>
#include <cuda_bf16.h>
#include <cstdio>

// Problem constants
#define B_   4
#define C_   256
#define CK_  448
#define N_   4096
#define NEGV (-1e15f)

// ---------------- scratch (device globals; no runtime allocation) ----------------
__device__ float g_Q [(size_t)B_ * N_ * CK_];   // [b][n][ck]   (Fq)
__device__ float g_KT[(size_t)B_ * CK_ * N_];   // [b][ck][n]   (G, key-transposed)
__device__ float g_V [(size_t)B_ * N_ * C_];    // [b][n][c]    (Hv)
__device__ float g_cmean[B_ * C_];
__device__ float g_crstd[B_ * C_];

// ---------------- packed f32x2 helpers (Blackwell FFMA2 path) ----------------
typedef unsigned long long u64v;
__device__ __forceinline__ u64v pk2(float x, float y) {
    u64v r; asm("mov.b64 %0, {%1, %2};" : "=l"(r) : "f"(x), "f"(y)); return r;
}
__device__ __forceinline__ void upk2(u64v v, float& x, float& y) {
    asm("mov.b64 {%0, %1}, %2;" : "=f"(x), "=f"(y) : "l"(v));
}
__device__ __forceinline__ u64v ffma2(u64v a, u64v b, u64v c) {
    u64v d; asm("fma.rn.f32x2 %0, %1, %2, %3;" : "=l"(d) : "l"(a), "l"(b), "l"(c)); return d;
}
__device__ __forceinline__ u64v fmul2(u64v a, u64v b) {
    u64v d; asm("mul.rn.f32x2 %0, %1, %2;" : "=l"(d) : "l"(a), "l"(b)); return d;
}

// ---------------- kernel 1: per-(b,c) mean / rstd of content (mvn stats) ----------------
__global__ __launch_bounds__(256) void stats_kernel(const float* __restrict__ content) {
    int bc = blockIdx.x;                    // 0..B_*C_-1
    const float4* x = (const float4*)(content + (size_t)bc * N_);
    int tid = threadIdx.x;
    float s = 0.f, q = 0.f;
    for (int i = tid; i < N_ / 4; i += 256) {
        float4 v = x[i];
        s += v.x + v.y + v.z + v.w;
        q += v.x * v.x + v.y * v.y + v.z * v.z + v.w * v.w;
    }
    // warp reduce
    #pragma unroll
    for (int off = 16; off; off >>= 1) {
        s += __shfl_xor_sync(0xffffffffu, s, off);
        q += __shfl_xor_sync(0xffffffffu, q, off);
    }
    __shared__ float ss[8], qq[8];
    int wid = tid >> 5, lane = tid & 31;
    if (lane == 0) { ss[wid] = s; qq[wid] = q; }
    __syncthreads();
    if (tid == 0) {
        float S = 0.f, Q = 0.f;
        #pragma unroll
        for (int i = 0; i < 8; i++) { S += ss[i]; Q += qq[i]; }
        float mean = S / (float)N_;
        float var  = (Q - (float)N_ * mean * mean) / (float)(N_ - 1);   // unbiased (ddof=1)
        g_cmean[bc] = mean;
        g_crstd[bc] = rsqrtf(var + 1e-5f);
    }
}

// ---------------- kernel 2: 1x1-conv projection GEMM ----------------
// Y[b,n,o] = sum_c X[b,c,n] * W[o,c] + bias[o]
// TRANS=false: Y stored [b][n][o] (stride Cout). TRANS=true: Y stored [b][o][n] (stride N_).
template<int CIN, bool TRANS>
__global__ __launch_bounds__(256) void proj_kernel(const float* __restrict__ X,
                                                   const float* __restrict__ W,
                                                   const float* __restrict__ bias,
                                                   float* __restrict__ Y, int Cout) {
    __shared__ float Xs[32 * 64];   // [cc][n]
    __shared__ float Ws[32 * 64];   // [cc][o]  (transposed on load)
    int b  = blockIdx.z;
    int n0 = blockIdx.x * 64;
    int o0 = blockIdx.y * 64;
    int tid = threadIdx.x;
    int tx = tid & 15;              // -> o group (4 o's)
    int ty = tid >> 4;              // -> n group (4 n's)

    u64v acc2[2][4];                // [n-pair][o]  pairs over n: (0,1),(2,3)
    #pragma unroll
    for (int p = 0; p < 2; p++)
        #pragma unroll
        for (int j = 0; j < 4; j++) acc2[p][j] = 0ull;

    for (int c0 = 0; c0 < CIN; c0 += 32) {
        __syncthreads();
        // X tile: 32c x 64n, contiguous along n
        for (int e = tid; e < 512; e += 256) {
            int cc = e >> 4, nn = (e & 15) << 2;
            *(float4*)&Xs[cc * 64 + nn] =
                *(const float4*)&X[((size_t)(b * CIN + c0 + cc)) * N_ + n0 + nn];
        }
        // W tile transposed: read W[o][c] along c, scatter to Ws[c][o]
        for (int e = tid; e < 512; e += 256) {
            int oo = e >> 3, c4 = (e & 7) << 2;
            float4 v = *(const float4*)&W[(size_t)(o0 + oo) * CIN + c0 + c4];
            Ws[(c4 + 0) * 64 + oo] = v.x;
            Ws[(c4 + 1) * 64 + oo] = v.y;
            Ws[(c4 + 2) * 64 + oo] = v.z;
            Ws[(c4 + 3) * 64 + oo] = v.w;
        }
        __syncthreads();
        #pragma unroll 8
        for (int cc = 0; cc < 32; cc++) {
            u64v xp0 = *(const u64v*)&Xs[cc * 64 + ty * 4];
            u64v xp1 = *(const u64v*)&Xs[cc * 64 + ty * 4 + 2];
            float4 w4 = *(const float4*)&Ws[cc * 64 + tx * 4];
            u64v w0 = pk2(w4.x, w4.x), w1 = pk2(w4.y, w4.y);
            u64v w2 = pk2(w4.z, w4.z), w3 = pk2(w4.w, w4.w);
            acc2[0][0] = ffma2(xp0, w0, acc2[0][0]);
            acc2[0][1] = ffma2(xp0, w1, acc2[0][1]);
            acc2[0][2] = ffma2(xp0, w2, acc2[0][2]);
            acc2[0][3] = ffma2(xp0, w3, acc2[0][3]);
            acc2[1][0] = ffma2(xp1, w0, acc2[1][0]);
            acc2[1][1] = ffma2(xp1, w1, acc2[1][1]);
            acc2[1][2] = ffma2(xp1, w2, acc2[1][2]);
            acc2[1][3] = ffma2(xp1, w3, acc2[1][3]);
        }
    }
    float a[4][4];
    #pragma unroll
    for (int p = 0; p < 2; p++)
        #pragma unroll
        for (int j = 0; j < 4; j++) upk2(acc2[p][j], a[2 * p][j], a[2 * p + 1][j]);
    float4 bo = *(const float4*)&bias[o0 + tx * 4];
    float bb[4] = {bo.x, bo.y, bo.z, bo.w};
    if (!TRANS) {
        #pragma unroll
        for (int i = 0; i < 4; i++) {
            float4 st = {a[i][0] + bb[0], a[i][1] + bb[1], a[i][2] + bb[2], a[i][3] + bb[3]};
            *(float4*)&Y[((size_t)(b * N_) + n0 + ty * 4 + i) * Cout + o0 + tx * 4] = st;
        }
    } else {
        #pragma unroll
        for (int j = 0; j < 4; j++) {
            float4 st = {a[0][j] + bb[j], a[1][j] + bb[j], a[2][j] + bb[j], a[3][j] + bb[j]};
            *(float4*)&Y[((size_t)(b * Cout) + o0 + tx * 4 + j) * N_ + n0 + ty * 4] = st;
        }
    }
}

// ---------------- kernel 3: fused masked flash-attention + epilogue ----------------
// CTA: batch b, 32 query rows. Loop over 32 key tiles of 128 keys.
// SMEM float offsets
#define QS_OFF  0            // [32][449]
#define KS_OFF  14368        // [64][128]   (K^T chunk: [ck][key])
#define VS_OFF  22560        // [128][64]
#define PS_OFF  30752        // [32][128]
#define SMK_OFF 34848        // [128] ints
#define SMEM_FLOATS 34976
#define SMEM_BYTES  (SMEM_FLOATS * 4)

__global__ __launch_bounds__(256, 1) void attn_kernel(const float* __restrict__ content,
                                                      const int* __restrict__ cmask,
                                                      const int* __restrict__ smask,
                                                      float* __restrict__ out) {
    extern __shared__ float sm[];
    float* Qs = sm + QS_OFF;
    float* Ks = sm + KS_OFF;
    float* Vs = sm + VS_OFF;
    float* Ps = sm + PS_OFF;
    int*   smk = (int*)(sm + SMK_OFF);

    int b  = blockIdx.y;
    int n0 = blockIdx.x * 32;
    int tid = threadIdx.x;
    int tx = tid & 15;       // key-col group (S) / channel group (PV)
    int ty = tid >> 4;       // owns query rows ty and ty+16

    // load Q tile [32][448] -> Qs stride 449 (conflict-free scalar reads)
    for (int e = tid; e < 32 * 112; e += 256) {
        int r = e / 112, o4 = (e % 112) * 4;
        float4 v = *(const float4*)&g_Q[((size_t)b * N_ + n0 + r) * CK_ + o4];
        float* dst = &Qs[r * 449 + o4];
        dst[0] = v.x; dst[1] = v.y; dst[2] = v.z; dst[3] = v.w;
    }
    int cmr0 = cmask[b * N_ + n0 + ty]      != 0;
    int cmr1 = cmask[b * N_ + n0 + ty + 16] != 0;

    float mrow[2] = {-3.4e38f, -3.4e38f};
    float lrow[2] = {0.f, 0.f};
    u64v accM[2][8], accQ[2][8];   // [row][vc*2+h]: packed channel pairs; mean-acc & m2-acc
    #pragma unroll
    for (int r = 0; r < 2; r++)
        #pragma unroll
        for (int h = 0; h < 8; h++) { accM[r][h] = 0ull; accQ[r][h] = 0ull; }

    for (int kt = 0; kt < 32; kt++) {
        int k0 = kt * 128;
        if (tid < 128) smk[tid] = (smask[b * N_ + k0 + tid] == 0);

        // ---- S = Q K^T over 7 chunks of 64 ck ----
        u64v s2[2][4];
        #pragma unroll
        for (int r = 0; r < 2; r++)
            #pragma unroll
            for (int g = 0; g < 4; g++) s2[r][g] = 0ull;

        for (int ckc = 0; ckc < 7; ckc++) {
            __syncthreads();
            for (int e = tid; e < 64 * 32; e += 256) {
                int cc = e >> 5, k4 = (e & 31) << 2;
                *(float4*)&Ks[cc * 128 + k4] =
                    *(const float4*)&g_KT[((size_t)b * CK_ + ckc * 64 + cc) * N_ + k0 + k4];
            }
            __syncthreads();
            const float* qp0 = &Qs[ty * 449 + ckc * 64];
            const float* qp1 = &Qs[(ty + 16) * 449 + ckc * 64];
            #pragma unroll 8
            for (int cc = 0; cc < 64; cc++) {
                u64v q0 = pk2(qp0[cc], qp0[cc]);
                u64v q1 = pk2(qp1[cc], qp1[cc]);
                const u64v* krow = (const u64v*)&Ks[cc * 128];
                u64v ka = krow[tx * 2], kb = krow[tx * 2 + 1];
                u64v kc = krow[32 + tx * 2], kd = krow[32 + tx * 2 + 1];
                s2[0][0] = ffma2(q0, ka, s2[0][0]);
                s2[0][1] = ffma2(q0, kb, s2[0][1]);
                s2[0][2] = ffma2(q0, kc, s2[0][2]);
                s2[0][3] = ffma2(q0, kd, s2[0][3]);
                s2[1][0] = ffma2(q1, ka, s2[1][0]);
                s2[1][1] = ffma2(q1, kb, s2[1][1]);
                s2[1][2] = ffma2(q1, kc, s2[1][2]);
                s2[1][3] = ffma2(q1, kd, s2[1][3]);
            }
        }

        // ---- mask + online softmax (rows ty, ty+16; 16 lanes per row) ----
        float s[2][8];
        #pragma unroll
        for (int r = 0; r < 2; r++)
            #pragma unroll
            for (int g = 0; g < 4; g++) upk2(s2[r][g], s[r][2 * g], s[r][2 * g + 1]);

        #pragma unroll
        for (int r = 0; r < 2; r++) {
            int cm = (r == 0) ? cmr0 : cmr1;
            if (cm) {
                #pragma unroll
                for (int j = 0; j < 8; j++) {
                    int col = (j < 4) ? (tx * 4 + j) : (64 + tx * 4 + j - 4);
                    if (smk[col]) s[r][j] = NEGV;
                }
            }
            float mloc = s[r][0];
            #pragma unroll
            for (int j = 1; j < 8; j++) mloc = fmaxf(mloc, s[r][j]);
            #pragma unroll
            for (int off = 8; off; off >>= 1)
                mloc = fmaxf(mloc, __shfl_xor_sync(0xffffffffu, mloc, off));
            float mnew = fmaxf(mrow[r], mloc);
            float scf  = __expf(mrow[r] - mnew);
            mrow[r] = mnew;
            float ps = 0.f, p[8];
            #pragma unroll
            for (int j = 0; j < 8; j++) { p[j] = __expf(s[r][j] - mnew); ps += p[j]; }
            lrow[r] = lrow[r] * scf + ps;
            int rr = (r == 0) ? ty : (ty + 16);
            #pragma unroll
            for (int j = 0; j < 8; j++) {
                int col = (j < 4) ? (tx * 4 + j) : (64 + tx * 4 + j - 4);
                Ps[rr * 128 + col] = p[j];
            }
            u64v scp = pk2(scf, scf);
            #pragma unroll
            for (int h = 0; h < 8; h++) {
                accM[r][h] = fmul2(accM[r][h], scp);
                accQ[r][h] = fmul2(accQ[r][h], scp);
            }
        }
        __syncthreads();

        // ---- PV: accumulate P*V and P*V^2 over 4 channel chunks ----
        #pragma unroll
        for (int vc = 0; vc < 4; vc++) {
            for (int e = tid; e < 128 * 16; e += 256) {
                int key = e >> 4, c4 = (e & 15) << 2;
                *(float4*)&Vs[key * 64 + c4] =
                    *(const float4*)&g_V[((size_t)b * N_ + k0 + key) * C_ + vc * 64 + c4];
            }
            __syncthreads();
            const u64v* vsb = (const u64v*)Vs;
            #pragma unroll 4
            for (int m = 0; m < 128; m++) {
                float p0f = Ps[ty * 128 + m];
                float p1f = Ps[(ty + 16) * 128 + m];
                u64v p0 = pk2(p0f, p0f), p1 = pk2(p1f, p1f);
                u64v va = vsb[m * 32 + tx * 2], vb = vsb[m * 32 + tx * 2 + 1];
                u64v va2 = fmul2(va, va), vb2 = fmul2(vb, vb);
                accM[0][vc * 2]     = ffma2(p0, va,  accM[0][vc * 2]);
                accM[0][vc * 2 + 1] = ffma2(p0, vb,  accM[0][vc * 2 + 1]);
                accQ[0][vc * 2]     = ffma2(p0, va2, accQ[0][vc * 2]);
                accQ[0][vc * 2 + 1] = ffma2(p0, vb2, accQ[0][vc * 2 + 1]);
                accM[1][vc * 2]     = ffma2(p1, va,  accM[1][vc * 2]);
                accM[1][vc * 2 + 1] = ffma2(p1, vb,  accM[1][vc * 2 + 1]);
                accQ[1][vc * 2]     = ffma2(p1, va2, accQ[1][vc * 2]);
                accQ[1][vc * 2 + 1] = ffma2(p1, vb2, accQ[1][vc * 2 + 1]);
            }
            __syncthreads();
        }
    }

    // ---- finalize: mean/std + mvn epilogue, write [b][c][n] ----
    #pragma unroll
    for (int r = 0; r < 2; r++) {
        float lt = lrow[r];
        #pragma unroll
        for (int off = 8; off; off >>= 1) lt += __shfl_xor_sync(0xffffffffu, lt, off);
        float inv = 1.0f / lt;
        int n = n0 + ((r == 0) ? ty : (ty + 16));
        #pragma unroll
        for (int vc = 0; vc < 4; vc++) {
            #pragma unroll
            for (int h = 0; h < 2; h++) {
                float m0, m1, q0, q1;
                upk2(accM[r][vc * 2 + h], m0, m1);
                upk2(accQ[r][vc * 2 + h], q0, q1);
                int ch0 = vc * 64 + tx * 4 + h * 2;
                #pragma unroll
                for (int e = 0; e < 2; e++) {
                    float mean = ((e == 0) ? m0 : m1) * inv;
                    float m2   = ((e == 0) ? q0 : q1) * inv;
                    float sd = sqrtf(fmaxf(m2 - mean * mean, 0.f));
                    int ch = ch0 + e;
                    size_t oi = ((size_t)(b * C_ + ch)) * N_ + n;
                    float cx = content[oi];
                    out[oi] = sd * (cx - g_cmean[b * C_ + ch]) * g_crstd[b * C_ + ch] + mean;
                }
            }
        }
    }
}

// ---------------- launch ----------------
extern "C" void kernel_launch(void* const* d_in, const int* in_sizes, int n_in,
                              void* d_out, int out_size) {
    const float* content     = (const float*)d_in[0];
    const float* style       = (const float*)d_in[1];
    const float* content_key = (const float*)d_in[2];
    const float* style_key   = (const float*)d_in[3];
    const int*   cmask       = (const int*)d_in[4];
    const int*   smask       = (const int*)d_in[5];
    const float* Wf = (const float*)d_in[6];
    const float* bf = (const float*)d_in[7];
    const float* Wg = (const float*)d_in[8];
    const float* bg = (const float*)d_in[9];
    const float* Wh = (const float*)d_in[10];
    const float* bh = (const float*)d_in[11];
    float* out = (float*)d_out;

    float *Qp, *KTp, *Vp;
    cudaGetSymbolAddress((void**)&Qp,  g_Q);
    cudaGetSymbolAddress((void**)&KTp, g_KT);
    cudaGetSymbolAddress((void**)&Vp,  g_V);
    cudaFuncSetAttribute(attn_kernel, cudaFuncAttributeMaxDynamicSharedMemorySize, SMEM_BYTES);

    stats_kernel<<<B_ * C_, 256>>>(content);
    proj_kernel<CK_, false><<<dim3(N_ / 64, CK_ / 64, B_), 256>>>(content_key, Wf, bf, Qp, CK_);
    proj_kernel<CK_, true ><<<dim3(N_ / 64, CK_ / 64, B_), 256>>>(style_key,   Wg, bg, KTp, CK_);
    proj_kernel<C_,  false><<<dim3(N_ / 64, C_  / 64, B_), 256>>>(style,       Wh, bh, Vp, C_);
    attn_kernel<<<dim3(N_ / 32, B_), 256, SMEM_BYTES>>>(content, cmask, smask, out);
}